// round 1
// baseline (speedup 1.0000x reference)
#include <cuda_runtime.h>
#include <math.h>

// Scratch (allocation-free rule: __device__ globals)
__device__ float g_pooled[16 * 16 * 64];   // [B][nH][hd]
__device__ float g_delta [16 * 16 * 64];   // [B][nH][hd]

// ---------------------------------------------------------------------------
// Kernel 1: mean-pool over H*W (4096 contiguous floats per row).
// One warp per row. 8 warps / block -> 2048 blocks of 256 threads.
// ---------------------------------------------------------------------------
__global__ void pool_kernel(const float* __restrict__ x) {
    const int warp_id = (blockIdx.x * (blockDim.x >> 5)) + (threadIdx.x >> 5);
    const int lane = threadIdx.x & 31;
    if (warp_id >= 16 * 16 * 64) return;

    const float4* row = reinterpret_cast<const float4*>(x + (size_t)warp_id * 4096);
    float s = 0.f;
    #pragma unroll 8
    for (int j = lane; j < 1024; j += 32) {
        float4 v = row[j];
        s += (v.x + v.y) + (v.z + v.w);
    }
    #pragma unroll
    for (int o = 16; o > 0; o >>= 1)
        s += __shfl_down_sync(0xffffffffu, s, o);
    if (lane == 0)
        g_pooled[warp_id] = s * (1.0f / 4096.0f);
}

// ---------------------------------------------------------------------------
// Kernel 2: compress -> MHA (2 heads, L=16, E=4) -> out_proj -> expand ->
//           residual+gate -> LayerNorm -> delta.  One block per batch b.
// ---------------------------------------------------------------------------
__global__ void mid_kernel(const float* __restrict__ compress_w,   // [4,64]
                           const float* __restrict__ compress_b,   // [4]
                           const float* __restrict__ in_proj_w,    // [12,4]
                           const float* __restrict__ in_proj_b,    // [12]
                           const float* __restrict__ out_proj_w,   // [4,4]
                           const float* __restrict__ out_proj_b,   // [4]
                           const float* __restrict__ expand_w,     // [64,4]
                           const float* __restrict__ expand_b,     // [64]
                           const float* __restrict__ ln_w,         // [64]
                           const float* __restrict__ ln_b,         // [64]
                           const float* __restrict__ gate)         // [1]
{
    const int b = blockIdx.x;     // 0..15
    const int tid = threadIdx.x;  // 0..127

    __shared__ float sp[16][64];    // pooled (residual)
    __shared__ float sxc[16][4];    // compressed
    __shared__ float sqkv[16][12];  // q|k|v
    __shared__ float so[16][4];     // attention output
    __shared__ float sat[16][4];    // out_proj output
    __shared__ float sy[16][64];    // residual + gate*expand

    // load pooled
    for (int i = tid; i < 1024; i += 128)
        sp[i >> 6][i & 63] = g_pooled[b * 1024 + i];
    __syncthreads();

    // compress: [16,64] @ [64->4]
    if (tid < 64) {
        const int l = tid >> 2, e = tid & 3;
        float s = compress_b[e];
        #pragma unroll
        for (int j = 0; j < 64; j++) s += sp[l][j] * compress_w[e * 64 + j];
        sxc[l][e] = s;
    }
    __syncthreads();

    // qkv projection: [16,4] @ [4->12]
    for (int idx = tid; idx < 192; idx += 128) {
        const int l = idx / 12, r = idx % 12;
        float s = in_proj_b[r];
        #pragma unroll
        for (int e = 0; e < 4; e++) s += sxc[l][e] * in_proj_w[r * 4 + e];
        sqkv[l][r] = s;
    }
    __syncthreads();

    // attention: 2 heads, dh=2, L=16. One thread per (head, query).
    if (tid < 32) {
        const int h = tid >> 4, q = tid & 15;
        const int d0 = h * 2, d1 = h * 2 + 1;
        const float scale = 0.70710678118654752440f; // 1/sqrt(2)
        float sc[16], m = -1e30f;
        #pragma unroll
        for (int j = 0; j < 16; j++) {
            float v = (sqkv[q][d0] * sqkv[j][4 + d0] +
                       sqkv[q][d1] * sqkv[j][4 + d1]) * scale;
            sc[j] = v;
            m = fmaxf(m, v);
        }
        float denom = 0.f;
        #pragma unroll
        for (int j = 0; j < 16; j++) { sc[j] = __expf(sc[j] - m); denom += sc[j]; }
        const float inv = 1.0f / denom;
        float o0 = 0.f, o1 = 0.f;
        #pragma unroll
        for (int j = 0; j < 16; j++) {
            const float a = sc[j] * inv;
            o0 += a * sqkv[j][8 + d0];
            o1 += a * sqkv[j][8 + d1];
        }
        so[q][d0] = o0;
        so[q][d1] = o1;
    }
    __syncthreads();

    // out_proj: [16,4] @ [4->4]
    if (tid < 64) {
        const int l = tid >> 2, e = tid & 3;
        float s = out_proj_b[e];
        #pragma unroll
        for (int j = 0; j < 4; j++) s += so[l][j] * out_proj_w[e * 4 + j];
        sat[l][e] = s;
    }
    __syncthreads();

    // expand + residual + gate
    const float g = gate[0];
    for (int i = tid; i < 1024; i += 128) {
        const int l = i >> 6, c = i & 63;
        float s = expand_b[c];
        #pragma unroll
        for (int j = 0; j < 4; j++) s += sat[l][j] * expand_w[c * 4 + j];
        sy[l][c] = sp[l][c] + g * s;
    }
    __syncthreads();

    // LayerNorm over hd=64, then delta = ln_out - residual
    if (tid < 16) {
        const int l = tid;
        float mu = 0.f;
        #pragma unroll
        for (int c = 0; c < 64; c++) mu += sy[l][c];
        mu *= (1.0f / 64.0f);
        float var = 0.f;
        #pragma unroll
        for (int c = 0; c < 64; c++) {
            const float d = sy[l][c] - mu;
            var += d * d;
        }
        var *= (1.0f / 64.0f);
        const float inv = rsqrtf(var + 1e-5f);
        #pragma unroll
        for (int c = 0; c < 64; c++) {
            const float o = (sy[l][c] - mu) * inv * ln_w[c] + ln_b[c];
            g_delta[b * 1024 + l * 64 + c] = o - sp[l][c];
        }
    }
}

// ---------------------------------------------------------------------------
// Kernel 3: out = x + delta[row], row = linear_index / 4096. float4 streams.
// ---------------------------------------------------------------------------
__global__ void add_kernel(const float* __restrict__ x, float* __restrict__ out) {
    const size_t i4 = (size_t)blockIdx.x * blockDim.x + threadIdx.x; // float4 index
    // n4 = 16777216 exactly matches grid; no bound check needed, but keep safe:
    const float d = g_delta[i4 >> 10];  // 1024 float4 per pooled row
    const float4 v = reinterpret_cast<const float4*>(x)[i4];
    float4 r;
    r.x = v.x + d; r.y = v.y + d; r.z = v.z + d; r.w = v.w + d;
    reinterpret_cast<float4*>(out)[i4] = r;
}

extern "C" void kernel_launch(void* const* d_in, const int* in_sizes, int n_in,
                              void* d_out, int out_size) {
    const float* x          = (const float*)d_in[0];
    const float* compress_w = (const float*)d_in[1];
    const float* compress_b = (const float*)d_in[2];
    const float* in_proj_w  = (const float*)d_in[3];
    const float* in_proj_b  = (const float*)d_in[4];
    const float* out_proj_w = (const float*)d_in[5];
    const float* out_proj_b = (const float*)d_in[6];
    const float* expand_w   = (const float*)d_in[7];
    const float* expand_b   = (const float*)d_in[8];
    const float* ln_w       = (const float*)d_in[9];
    const float* ln_b       = (const float*)d_in[10];
    const float* gate       = (const float*)d_in[11];
    float* out = (float*)d_out;

    // 1) pool: 16384 rows, 1 warp each, 8 warps/block
    pool_kernel<<<2048, 256>>>(x);

    // 2) tiny middle math: 1 block per batch
    mid_kernel<<<16, 128>>>(compress_w, compress_b, in_proj_w, in_proj_b,
                            out_proj_w, out_proj_b, expand_w, expand_b,
                            ln_w, ln_b, gate);

    // 3) broadcast add: 16,777,216 float4 elements
    add_kernel<<<65536, 256>>>(x, out);
}